// round 2
// baseline (speedup 1.0000x reference)
#include <cuda_runtime.h>
#include <math.h>

#define Bn 256
#define Tn 250
#define Zn 128
#define Hn 256
#define Dn 512
#define Kn 20
#define Pn 123
#define TB (Tn*Bn)

typedef unsigned long long ull;

// ---------------- scratch (transposed layouts: [unit][batch]) -------------
__device__ float g_hfT[2][Hn*Bn];
__device__ float g_cfT[Hn*Bn];
__device__ float g_hbT[2][Hn*Bn];
__device__ float g_cbT[Hn*Bn];
__device__ float g_z  [Bn*Zn];
__device__ float g_zgT[4*Dn*Bn];        // [gatecol][batch]
__device__ float g_hdT[2][Dn*Bn];
__device__ float g_cdT[Dn*Bn];
__device__ float g_hsT[(size_t)Dn*TB];  // [unit][t*Bn+b]

__device__ __forceinline__ float sigf(float x) { return 1.0f / (1.0f + expf(-x)); }

__device__ __forceinline__ void ffma2(ull& d, ull a, ull b) {
    asm("fma.rn.f32x2 %0, %1, %2, %0;" : "+l"(d) : "l"(a), "l"(b));
}
__device__ __forceinline__ ull dup2(float w) {
    ull r; unsigned int u = __float_as_uint(w);
    asm("mov.b64 %0, {%1, %1};" : "=l"(r) : "r"(u));
    return r;
}

// ---------------- init ------------------------------------------------------
__global__ void init_kernel() {
    int i = blockIdx.x * blockDim.x + threadIdx.x;
    if (i < Hn * Bn) {
        g_hfT[0][i] = 0.f; g_cfT[i] = 0.f;
        g_hbT[0][i] = 0.f; g_cbT[i] = 0.f;
    }
}

// ---------------- encoder step (both dirs, f32x2 GEMM) ----------------------
// CTA: 32 batch x 32 units (128 gate cols gathered). 256 threads.
// thread: 4 batch rows (2 f32x2 pairs) x 4 cols = the 4 gates of unit u0+tx.
__global__ __launch_bounds__(256) void enc_step(
    const float* __restrict__ data,
    const float* __restrict__ Wx_f, const float* __restrict__ Wh_f, const float* __restrict__ b_f,
    const float* __restrict__ Wx_b, const float* __restrict__ Wh_b, const float* __restrict__ b_b,
    int t)
{
    const int dir = blockIdx.z;
    const float* __restrict__ Wx  = dir ? Wx_b : Wx_f;
    const float* __restrict__ Wh  = dir ? Wh_b : Wh_f;
    const float* __restrict__ bb  = dir ? b_b  : b_f;
    const float* __restrict__ hin = dir ? g_hbT[t & 1] : g_hfT[t & 1];
    float* __restrict__ hout      = dir ? g_hbT[(t + 1) & 1] : g_hfT[(t + 1) & 1];
    float* __restrict__ cst       = dir ? g_cbT : g_cfT;
    const int xtime = dir ? (Tn - t) : (t + 1);

    __shared__ __align__(16) float As[2][32][32];   // [k][batchrow]
    __shared__ __align__(16) float Ws[2][32][128];  // [k][gathered col]
    __shared__ float Wxs[5][128];
    __shared__ float bsh[128];

    const int tid = threadIdx.x;
    const int tx = tid & 31;       // unit in tile
    const int ty = tid >> 5;       // 8 row groups of 4
    const int b0 = blockIdx.x * 32;
    const int u0 = blockIdx.y * 32;

    for (int i = tid; i < 5 * 128; i += 256) {
        int f = i >> 7, c = i & 127;
        Wxs[f][c] = Wx[f * (4 * Hn) + (c >> 5) * Hn + u0 + (c & 31)];
    }
    if (tid < 128) bsh[tid] = bb[(tid >> 5) * Hn + u0 + (tid & 31)];

    const int ak = tid >> 3, ac = (tid & 7) * 4;

    ull acc[2][4] = {};

    // stage 0 load
    float4 aReg = *(const float4*)&hin[ak * Bn + b0 + ac];
    float4 wReg[4];
    #pragma unroll
    for (int i = 0; i < 4; i++) {
        int slot = tid + 256 * i; int k = slot >> 5; int c = (slot & 31) * 4;
        wReg[i] = *(const float4*)&Wh[k * (4 * Hn) + (c >> 5) * Hn + u0 + (c & 31)];
    }
    *(float4*)&As[0][ak][ac] = aReg;
    #pragma unroll
    for (int i = 0; i < 4; i++) {
        int slot = tid + 256 * i; int k = slot >> 5; int c = (slot & 31) * 4;
        *(float4*)&Ws[0][k][c] = wReg[i];
    }
    __syncthreads();

    const int NS = Hn / 32;   // 8
    for (int s = 0; s < NS; s++) {
        const int buf = s & 1;
        if (s + 1 < NS) {
            const int k0 = (s + 1) * 32;
            aReg = *(const float4*)&hin[(k0 + ak) * Bn + b0 + ac];
            #pragma unroll
            for (int i = 0; i < 4; i++) {
                int slot = tid + 256 * i; int k = slot >> 5; int c = (slot & 31) * 4;
                wReg[i] = *(const float4*)&Wh[(k0 + k) * (4 * Hn) + (c >> 5) * Hn + u0 + (c & 31)];
            }
        }
        #pragma unroll
        for (int k = 0; k < 32; k++) {
            ull a0 = *(const ull*)&As[buf][k][ty * 4];
            ull a1 = *(const ull*)&As[buf][k][ty * 4 + 2];
            #pragma unroll
            for (int j = 0; j < 4; j++) {
                ull wd = dup2(Ws[buf][k][tx + 32 * j]);
                ffma2(acc[0][j], a0, wd);
                ffma2(acc[1][j], a1, wd);
            }
        }
        if (s + 1 < NS) {
            const int nb = (s + 1) & 1;
            *(float4*)&As[nb][ak][ac] = aReg;
            #pragma unroll
            for (int i = 0; i < 4; i++) {
                int slot = tid + 256 * i; int k = slot >> 5; int c = (slot & 31) * 4;
                *(float4*)&Ws[nb][k][c] = wReg[i];
            }
            __syncthreads();
        }
    }

    // epilogue: unit u, rows b0+4ty..+3
    const int u = u0 + tx;
    float4 cv = *(const float4*)&cst[u * Bn + b0 + ty * 4];
    float cr[4] = {cv.x, cv.y, cv.z, cv.w};
    float hr[4];
    #pragma unroll
    for (int r = 0; r < 4; r++) {
        int b = b0 + ty * 4 + r;
        const float* xp = &data[((size_t)b * (Tn + 1) + xtime) * 5];
        float x0 = xp[0], x1 = xp[1], x2 = xp[2], x3 = xp[3], x4 = xp[4];
        float p[4];
        #pragma unroll
        for (int g = 0; g < 4; g++) {
            float2 av = reinterpret_cast<float2&>(acc[r >> 1][g]);
            float s = ((r & 1) ? av.y : av.x) + bsh[tx + 32 * g];
            s = fmaf(x0, Wxs[0][tx + 32 * g], s);
            s = fmaf(x1, Wxs[1][tx + 32 * g], s);
            s = fmaf(x2, Wxs[2][tx + 32 * g], s);
            s = fmaf(x3, Wxs[3][tx + 32 * g], s);
            s = fmaf(x4, Wxs[4][tx + 32 * g], s);
            p[g] = s;
        }
        float c = sigf(p[1]) * cr[r] + sigf(p[0]) * tanhf(p[2]);
        hr[r] = sigf(p[3]) * tanhf(c);
        cr[r] = c;
    }
    *(float4*)&cst[u * Bn + b0 + ty * 4]  = make_float4(cr[0], cr[1], cr[2], cr[3]);
    *(float4*)&hout[u * Bn + b0 + ty * 4] = make_float4(hr[0], hr[1], hr[2], hr[3]);
}

// ---------------- decoder step (f32x2 GEMM) ---------------------------------
__global__ __launch_bounds__(256) void dec_step(
    const float* __restrict__ data,
    const float* __restrict__ dec_Wx, const float* __restrict__ Wh, int t)
{
    const float* __restrict__ hin = g_hdT[t & 1];
    float* __restrict__ hout      = g_hdT[(t + 1) & 1];

    __shared__ __align__(16) float As[2][32][32];
    __shared__ __align__(16) float Ws[2][32][128];
    __shared__ float Wxs[5][128];

    const int tid = threadIdx.x;
    const int tx = tid & 31;
    const int ty = tid >> 5;
    const int b0 = blockIdx.x * 32;
    const int u0 = blockIdx.y * 32;

    for (int i = tid; i < 5 * 128; i += 256) {
        int f = i >> 7, c = i & 127;
        Wxs[f][c] = dec_Wx[f * (4 * Dn) + (c >> 5) * Dn + u0 + (c & 31)];
    }

    const int ak = tid >> 3, ac = (tid & 7) * 4;

    ull acc[2][4] = {};

    float4 aReg = *(const float4*)&hin[ak * Bn + b0 + ac];
    float4 wReg[4];
    #pragma unroll
    for (int i = 0; i < 4; i++) {
        int slot = tid + 256 * i; int k = slot >> 5; int c = (slot & 31) * 4;
        wReg[i] = *(const float4*)&Wh[k * (4 * Dn) + (c >> 5) * Dn + u0 + (c & 31)];
    }
    *(float4*)&As[0][ak][ac] = aReg;
    #pragma unroll
    for (int i = 0; i < 4; i++) {
        int slot = tid + 256 * i; int k = slot >> 5; int c = (slot & 31) * 4;
        *(float4*)&Ws[0][k][c] = wReg[i];
    }
    __syncthreads();

    const int NS = Dn / 32;   // 16
    for (int s = 0; s < NS; s++) {
        const int buf = s & 1;
        if (s + 1 < NS) {
            const int k0 = (s + 1) * 32;
            aReg = *(const float4*)&hin[(k0 + ak) * Bn + b0 + ac];
            #pragma unroll
            for (int i = 0; i < 4; i++) {
                int slot = tid + 256 * i; int k = slot >> 5; int c = (slot & 31) * 4;
                wReg[i] = *(const float4*)&Wh[(k0 + k) * (4 * Dn) + (c >> 5) * Dn + u0 + (c & 31)];
            }
        }
        #pragma unroll
        for (int k = 0; k < 32; k++) {
            ull a0 = *(const ull*)&As[buf][k][ty * 4];
            ull a1 = *(const ull*)&As[buf][k][ty * 4 + 2];
            #pragma unroll
            for (int j = 0; j < 4; j++) {
                ull wd = dup2(Ws[buf][k][tx + 32 * j]);
                ffma2(acc[0][j], a0, wd);
                ffma2(acc[1][j], a1, wd);
            }
        }
        if (s + 1 < NS) {
            const int nb = (s + 1) & 1;
            *(float4*)&As[nb][ak][ac] = aReg;
            #pragma unroll
            for (int i = 0; i < 4; i++) {
                int slot = tid + 256 * i; int k = slot >> 5; int c = (slot & 31) * 4;
                *(float4*)&Ws[nb][k][c] = wReg[i];
            }
            __syncthreads();
        }
    }

    const int u = u0 + tx;
    float4 cv = *(const float4*)&g_cdT[u * Bn + b0 + ty * 4];
    float cr[4] = {cv.x, cv.y, cv.z, cv.w};
    float hr[4];
    float4 zr[4];
    #pragma unroll
    for (int g = 0; g < 4; g++)
        zr[g] = *(const float4*)&g_zgT[((size_t)g * Dn + u) * Bn + b0 + ty * 4];
    #pragma unroll
    for (int r = 0; r < 4; r++) {
        int b = b0 + ty * 4 + r;
        const float* xp = &data[((size_t)b * (Tn + 1) + t) * 5];
        float x0 = xp[0], x1 = xp[1], x2 = xp[2], x3 = xp[3], x4 = xp[4];
        float p[4];
        #pragma unroll
        for (int g = 0; g < 4; g++) {
            float2 av = reinterpret_cast<float2&>(acc[r >> 1][g]);
            const float* zf = (const float*)&zr[g];
            float s = ((r & 1) ? av.y : av.x) + zf[r];
            s = fmaf(x0, Wxs[0][tx + 32 * g], s);
            s = fmaf(x1, Wxs[1][tx + 32 * g], s);
            s = fmaf(x2, Wxs[2][tx + 32 * g], s);
            s = fmaf(x3, Wxs[3][tx + 32 * g], s);
            s = fmaf(x4, Wxs[4][tx + 32 * g], s);
            p[g] = s;
        }
        float c = sigf(p[1]) * cr[r] + sigf(p[0]) * tanhf(p[2]);
        hr[r] = sigf(p[3]) * tanhf(c);
        cr[r] = c;
    }
    *(float4*)&g_cdT[u * Bn + b0 + ty * 4] = make_float4(cr[0], cr[1], cr[2], cr[3]);
    *(float4*)&hout[u * Bn + b0 + ty * 4]  = make_float4(hr[0], hr[1], hr[2], hr[3]);
    *(float4*)&g_hsT[(size_t)u * TB + (size_t)t * Bn + b0 + ty * 4]
        = make_float4(hr[0], hr[1], hr[2], hr[3]);
}

// ---------------- latent stage 1 --------------------------------------------
__global__ void latent1(const float* __restrict__ W, const float* __restrict__ bias,
                        const float* __restrict__ eps,
                        float* __restrict__ zm, float* __restrict__ zl)
{
    int b = blockIdx.x, j = threadIdx.x;   // 128 threads
    float sm = bias[j], sl = bias[j + Zn];
    for (int k = 0; k < Hn; k++) {
        float a = g_hfT[0][k * Bn + b];
        sm = fmaf(a, W[k * (2 * Zn) + j], sm);
        sl = fmaf(a, W[k * (2 * Zn) + Zn + j], sl);
    }
    for (int k = 0; k < Hn; k++) {
        float a = g_hbT[0][k * Bn + b];
        sm = fmaf(a, W[(Hn + k) * (2 * Zn) + j], sm);
        sl = fmaf(a, W[(Hn + k) * (2 * Zn) + Zn + j], sl);
    }
    zm[b * Zn + j] = sm;
    zl[b * Zn + j] = sl;
    g_z[b * Zn + j] = sm + expf(0.5f * sl) * eps[b * Zn + j];
}

// ---------------- latent stage 2 --------------------------------------------
__global__ void latent2(const float* __restrict__ init_W, const float* __restrict__ init_b,
                        const float* __restrict__ dec_Wx, const float* __restrict__ dec_b)
{
    int b = blockIdx.x;
    int col = blockIdx.y * 256 + threadIdx.x;   // 0..3071
    __shared__ float zs[Zn];
    if (threadIdx.x < Zn) zs[threadIdx.x] = g_z[b * Zn + threadIdx.x];
    __syncthreads();
    if (col < 2 * Dn) {
        float s = init_b[col];
        for (int k = 0; k < Zn; k++) s = fmaf(zs[k], init_W[k * (2 * Dn) + col], s);
        s = tanhf(s);
        if (col < Dn) g_hdT[0][col * Bn + b] = s;
        else          g_cdT[(col - Dn) * Bn + b] = s;
    } else {
        int c2 = col - 2 * Dn;   // 0..2047
        float s = dec_b[c2];
        for (int k = 0; k < Zn; k++) s = fmaf(zs[k], dec_Wx[(5 + k) * (4 * Dn) + c2], s);
        g_zgT[(size_t)c2 * Bn + b] = s;
    }
}

// ---------------- output head -----------------------------------------------
__global__ __launch_bounds__(256) void mix_kernel(
    const float* __restrict__ Wm, const float* __restrict__ bm, float* __restrict__ out)
{
    __shared__ float As[32][33];
    __shared__ float Ws[32][128];
    __shared__ float ys[32 * 129];
    const int tid = threadIdx.x;
    const int tx = tid & 31, ty = tid >> 5;
    const int row0 = blockIdx.x * 32;
    float acc[4][4] = {};

    for (int k0 = 0; k0 < Dn; k0 += 32) {
        __syncthreads();
        {   // hsT layout: [k][row] -> coalesced float4 loads
            int k = tid >> 3, c = (tid & 7) * 4;
            float4 v = *(const float4*)&g_hsT[(size_t)(k0 + k) * TB + row0 + c];
            As[k][c] = v.x; As[k][c + 1] = v.y; As[k][c + 2] = v.z; As[k][c + 3] = v.w;
        }
        for (int i = tid; i < 32 * 128; i += 256) {
            int k = i >> 7, c = i & 127;
            Ws[k][c] = (c < Pn) ? Wm[(k0 + k) * Pn + c] : 0.f;
        }
        __syncthreads();
        #pragma unroll
        for (int k = 0; k < 32; k++) {
            float a0 = As[k][ty * 4 + 0], a1 = As[k][ty * 4 + 1];
            float a2 = As[k][ty * 4 + 2], a3 = As[k][ty * 4 + 3];
            float4 w = *(const float4*)&Ws[k][tx * 4];
            acc[0][0] = fmaf(a0, w.x, acc[0][0]); acc[0][1] = fmaf(a0, w.y, acc[0][1]);
            acc[0][2] = fmaf(a0, w.z, acc[0][2]); acc[0][3] = fmaf(a0, w.w, acc[0][3]);
            acc[1][0] = fmaf(a1, w.x, acc[1][0]); acc[1][1] = fmaf(a1, w.y, acc[1][1]);
            acc[1][2] = fmaf(a1, w.z, acc[1][2]); acc[1][3] = fmaf(a1, w.w, acc[1][3]);
            acc[2][0] = fmaf(a2, w.x, acc[2][0]); acc[2][1] = fmaf(a2, w.y, acc[2][1]);
            acc[2][2] = fmaf(a2, w.z, acc[2][2]); acc[2][3] = fmaf(a2, w.w, acc[2][3]);
            acc[3][0] = fmaf(a3, w.x, acc[3][0]); acc[3][1] = fmaf(a3, w.y, acc[3][1]);
            acc[3][2] = fmaf(a3, w.z, acc[3][2]); acc[3][3] = fmaf(a3, w.w, acc[3][3]);
        }
    }

    #pragma unroll
    for (int r = 0; r < 4; r++)
        #pragma unroll
        for (int c = 0; c < 4; c++) {
            int cc = tx * 4 + c;
            float v = acc[r][c] + ((cc < Pn) ? bm[cc] : 0.f);
            ys[(ty * 4 + r) * 129 + cc] = v;
        }
    __syncthreads();

    if (tid < 32) {
        int row = row0 + tid;          // = t*Bn + b
        int tt = row >> 8;
        int bb2 = row & 255;
        float* o = out + ((size_t)bb2 * Tn + tt) * Pn;
        const float* y = &ys[tid * 129];
        float m = y[0];
        #pragma unroll
        for (int j = 1; j < Kn; j++) m = fmaxf(m, y[j]);
        float e[Kn]; float s = 0.f;
        #pragma unroll
        for (int j = 0; j < Kn; j++) { e[j] = expf(y[j] - m); s += e[j]; }
        float inv = 1.f / s;
        #pragma unroll
        for (int j = 0; j < Kn; j++) o[j] = e[j] * inv;
        #pragma unroll
        for (int j = Kn; j < 3 * Kn; j++) o[j] = y[j];
        #pragma unroll
        for (int j = 3 * Kn; j < 5 * Kn; j++) o[j] = expf(y[j]);
        #pragma unroll
        for (int j = 5 * Kn; j < 6 * Kn; j++) o[j] = tanhf(y[j]);
        o[120] = y[120]; o[121] = y[121]; o[122] = y[122];
    }
}

// ---------------- launcher ---------------------------------------------------
extern "C" void kernel_launch(void* const* d_in, const int* in_sizes, int n_in,
                              void* d_out, int out_size)
{
    (void)in_sizes; (void)n_in; (void)out_size;
    const float* data      = (const float*)d_in[0];
    const float* eps       = (const float*)d_in[1];
    const float* enc_Wx_f  = (const float*)d_in[2];
    const float* enc_Wh_f  = (const float*)d_in[3];
    const float* enc_b_f   = (const float*)d_in[4];
    const float* enc_Wx_b  = (const float*)d_in[5];
    const float* enc_Wh_b  = (const float*)d_in[6];
    const float* enc_b_b   = (const float*)d_in[7];
    const float* enc_out_W = (const float*)d_in[8];
    const float* enc_out_b = (const float*)d_in[9];
    const float* init_W    = (const float*)d_in[10];
    const float* init_b    = (const float*)d_in[11];
    const float* dec_Wx    = (const float*)d_in[12];
    const float* dec_Wh    = (const float*)d_in[13];
    const float* dec_b     = (const float*)d_in[14];
    const float* mix_W     = (const float*)d_in[15];
    const float* mix_b     = (const float*)d_in[16];
    float* out = (float*)d_out;

    const size_t params_sz = (size_t)Bn * Tn * Pn;

    init_kernel<<<256, 256>>>();

    dim3 eg(Bn / 32, Hn / 32, 2);          // 8 x 8 x 2 = 128 CTAs
    for (int t = 0; t < Tn; t++)
        enc_step<<<eg, 256>>>(data, enc_Wx_f, enc_Wh_f, enc_b_f,
                              enc_Wx_b, enc_Wh_b, enc_b_b, t);

    latent1<<<Bn, 128>>>(enc_out_W, enc_out_b, eps,
                         out + params_sz, out + params_sz + (size_t)Bn * Zn);
    latent2<<<dim3(Bn, 12), 256>>>(init_W, init_b, dec_Wx, dec_b);

    dim3 dg(Bn / 32, Dn / 32, 1);          // 8 x 16 = 128 CTAs
    for (int t = 0; t < Tn; t++)
        dec_step<<<dg, 256>>>(data, dec_Wx, dec_Wh, t);

    mix_kernel<<<(TB) / 32, 256>>>(mix_W, mix_b, out);
}

// round 3
// speedup vs baseline: 1.5464x; 1.5464x over previous
#include <cuda_runtime.h>
#include <math.h>

#define Bn 256
#define Tn 250
#define Zn 128
#define Hn 256
#define Dn 512
#define Kn 20
#define Pn 123
#define TB (Tn*Bn)

typedef unsigned long long ull;

// ---------------- scratch ---------------------------------------------------
__device__ float g_hfT[2][Hn*Bn];   // [unit][batch]
__device__ float g_hbT[2][Hn*Bn];
__device__ float g_z  [Bn*Zn];
__device__ float g_zgT[4*Dn*Bn];    // [gatecol][batch] (includes dec_b)
__device__ float g_hdT[2][Dn*Bn];
__device__ float g_cdT[Dn*Bn];
__device__ float g_hsT[(size_t)Dn*TB];
__device__ int   g_bar[32];

__device__ __forceinline__ float sigf(float x) { return 1.0f / (1.0f + expf(-x)); }
__device__ __forceinline__ void ffma2(ull& d, ull a, ull b) {
    asm("fma.rn.f32x2 %0, %1, %2, %0;" : "+l"(d) : "l"(a), "l"(b));
}
__device__ __forceinline__ ull dup2(float w) {
    ull r; unsigned int u = __float_as_uint(w);
    asm("mov.b64 %0, {%1, %1};" : "=l"(r) : "r"(u));
    return r;
}
__device__ __forceinline__ float2 unpk(ull v) {
    float2 f; asm("mov.b64 {%0, %1}, %2;" : "=f"(f.x), "=f"(f.y) : "l"(v));
    return f;
}

__global__ void init_bar() { if (threadIdx.x < 32) g_bar[threadIdx.x] = 0; }

__device__ __forceinline__ void grp_barrier(int* ctr, int target) {
    __syncthreads();
    if (threadIdx.x == 0) {
        __threadfence();
        atomicAdd(ctr, 1);
        while (*(volatile int*)ctr < target) { }
    }
    __syncthreads();
}

// =================== persistent encoder =====================================
// 128 CTAs: dir(2) x btile(8, 32 batch) x utile(8, 32 units -> 128 gate cols)
// smem: Wsm[262][128] (Wh + Wx + bias rows), Asm[262][32] (h + x + 1 rows)
#define EKR 262
#define ENC_SMEM ((EKR*128 + EKR*32) * 4)

__global__ __launch_bounds__(256) void enc_persist(
    const float* __restrict__ data,
    const float* __restrict__ Wx_f, const float* __restrict__ Wh_f, const float* __restrict__ b_f,
    const float* __restrict__ Wx_b, const float* __restrict__ Wh_b, const float* __restrict__ b_b)
{
    extern __shared__ float smem[];
    float* Wsm = smem;              // [262][128], col = unit*4 + gate
    float* Asm = smem + EKR * 128;  // [262][32]

    const int tid = threadIdx.x;
    const int bx  = blockIdx.x;
    const int dir = bx >> 6;
    const int bt  = (bx >> 3) & 7;
    const int ut  = bx & 7;
    const int b0  = bt * 32, u0 = ut * 32;

    const float* __restrict__ Wh = dir ? Wh_b : Wh_f;
    const float* __restrict__ Wx = dir ? Wx_b : Wx_f;
    const float* __restrict__ bb = dir ? b_b  : b_f;
    float* hbuf0 = dir ? g_hbT[0] : g_hfT[0];
    float* hbuf1 = dir ? g_hbT[1] : g_hfT[1];
    int* ctr = &g_bar[dir * 8 + bt];

    // one-time weight stage
    for (int i = tid; i < EKR * 128; i += 256) {
        int k = i >> 7, c = i & 127;
        int u = c >> 2, g = c & 3;
        float v;
        if (k < 256)      v = Wh[k * (4 * Hn) + g * Hn + u0 + u];
        else if (k < 261) v = Wx[(k - 256) * (4 * Hn) + g * Hn + u0 + u];
        else              v = bb[g * Hn + u0 + u];
        Wsm[i] = v;
    }

    const int tx = tid & 31;   // unit
    const int ty = tid >> 5;   // batch group (4 rows)
    const int u  = u0 + tx;

    // zero initial h (parity-0 buffer slice this group will read)
    {
        int uz = tid >> 3, c4 = (tid & 7) * 4;
        __stcg((float4*)&hbuf0[(u0 + uz) * Bn + b0 + c4], make_float4(0, 0, 0, 0));
    }
    float creg[4] = {0, 0, 0, 0};
    grp_barrier(ctr, 8);
    int s = 1;

    const int akr = tid >> 3, ac4 = (tid & 7) * 4;

    for (int t = 0; t < Tn; t++) {
        const float* hin = (t & 1) ? hbuf1 : hbuf0;
        float* hout      = (t & 1) ? hbuf0 : hbuf1;
        const int xtime  = dir ? (Tn - t) : (t + 1);

        float4 tmp[8];
        #pragma unroll
        for (int i = 0; i < 8; i++)
            tmp[i] = __ldcg((const float4*)&hin[(akr + 32 * i) * Bn + b0 + ac4]);
        #pragma unroll
        for (int i = 0; i < 8; i++)
            *(float4*)&Asm[(akr + 32 * i) * 32 + ac4] = tmp[i];
        if (tid < 160) {
            int j = tid >> 5, b = tid & 31;
            Asm[(256 + j) * 32 + b] =
                __ldg(&data[(size_t)(b0 + b) * ((Tn + 1) * 5) + xtime * 5 + j]);
        } else if (tid < 192) {
            Asm[261 * 32 + (tid - 160)] = 1.0f;
        }
        __syncthreads();

        ull acc0[4] = {}, acc1[4] = {};
        #pragma unroll 4
        for (int k = 0; k < EKR; k++) {
            ull a01 = *(const ull*)&Asm[k * 32 + ty * 4];
            ull a23 = *(const ull*)&Asm[k * 32 + ty * 4 + 2];
            float4 w = *(const float4*)&Wsm[k * 128 + tx * 4];
            ull w0 = dup2(w.x), w1 = dup2(w.y), w2 = dup2(w.z), w3 = dup2(w.w);
            ffma2(acc0[0], a01, w0); ffma2(acc1[0], a23, w0);
            ffma2(acc0[1], a01, w1); ffma2(acc1[1], a23, w1);
            ffma2(acc0[2], a01, w2); ffma2(acc1[2], a23, w2);
            ffma2(acc0[3], a01, w3); ffma2(acc1[3], a23, w3);
        }

        float pg[4][4];
        #pragma unroll
        for (int g = 0; g < 4; g++) {
            float2 v0 = unpk(acc0[g]);
            float2 v1 = unpk(acc1[g]);
            pg[0][g] = v0.x; pg[1][g] = v0.y; pg[2][g] = v1.x; pg[3][g] = v1.y;
        }
        float hreg[4];
        #pragma unroll
        for (int r = 0; r < 4; r++) {
            float cn = sigf(pg[r][1]) * creg[r] + sigf(pg[r][0]) * tanhf(pg[r][2]);
            hreg[r] = sigf(pg[r][3]) * tanhf(cn);
            creg[r] = cn;
        }
        __stcg((float4*)&hout[u * Bn + b0 + ty * 4],
               make_float4(hreg[0], hreg[1], hreg[2], hreg[3]));

        if (t < Tn - 1) { grp_barrier(ctr, 8 * (s + 1)); s++; }
    }
}

// =================== persistent decoder =====================================
// 128 CTAs: btile(4, 64 batch) x utile(32, 16 units -> 64 gate cols)
// smem: Wd[517][64] (Wh + Wx rows), Asm[261][64] (half-K chunk + x rows)
#define DKR 517
#define DEC_SMEM ((DKR*64 + 261*64) * 4)

__global__ __launch_bounds__(256) void dec_persist(
    const float* __restrict__ data,
    const float* __restrict__ dec_Wx, const float* __restrict__ Wh)
{
    extern __shared__ float smem[];
    float* Wd  = smem;              // [517][64], col = unit*4 + gate
    float* Asm = smem + DKR * 64;   // [261][64]

    const int tid = threadIdx.x;
    const int bt  = blockIdx.x >> 5;
    const int ut  = blockIdx.x & 31;
    const int b0  = bt * 64, u0 = ut * 16;
    int* ctr = &g_bar[16 + bt];

    for (int i = tid; i < DKR * 64; i += 256) {
        int k = i >> 6, c = i & 63;
        int uu = c >> 2, g = c & 3;
        float v;
        if (k < 512) v = Wh[k * (4 * Dn) + g * Dn + u0 + uu];
        else         v = dec_Wx[(k - 512) * (4 * Dn) + g * Dn + u0 + uu];
        Wd[i] = v;
    }

    const int tx = tid & 15;   // unit
    const int ty = tid >> 4;   // batch group (4 rows)
    const int u  = u0 + tx;

    float4 zr[4];
    #pragma unroll
    for (int g = 0; g < 4; g++)
        zr[g] = *(const float4*)&g_zgT[((size_t)g * Dn + u) * Bn + b0 + ty * 4];
    float4 cv = *(const float4*)&g_cdT[u * Bn + b0 + ty * 4];
    float creg[4] = {cv.x, cv.y, cv.z, cv.w};

    __syncthreads();
    int s = 0;
    const int akr = tid >> 4, ac4 = (tid & 15) * 4;

    for (int t = 0; t < Tn; t++) {
        const float* hin = (t & 1) ? g_hdT[1] : g_hdT[0];
        float* hout      = (t & 1) ? g_hdT[0] : g_hdT[1];
        ull acc0[4] = {}, acc1[4] = {};

        #pragma unroll 1
        for (int p = 0; p < 2; p++) {
            float4 tmp[16];
            #pragma unroll
            for (int i = 0; i < 16; i++)
                tmp[i] = __ldcg((const float4*)&hin[(size_t)(p * 256 + akr + 16 * i) * Bn + b0 + ac4]);
            #pragma unroll
            for (int i = 0; i < 16; i++)
                *(float4*)&Asm[(akr + 16 * i) * 64 + ac4] = tmp[i];
            if (p == 1) {
                for (int i = tid; i < 320; i += 256)
                    Asm[(256 + (i >> 6)) * 64 + (i & 63)] =
                        __ldg(&data[(size_t)(b0 + (i & 63)) * ((Tn + 1) * 5) + t * 5 + (i >> 6)]);
            }
            __syncthreads();

            const int KL = p ? 261 : 256;
            const float* Wp = Wd + p * 256 * 64;
            #pragma unroll 4
            for (int k = 0; k < KL; k++) {
                ull a01 = *(const ull*)&Asm[k * 64 + ty * 4];
                ull a23 = *(const ull*)&Asm[k * 64 + ty * 4 + 2];
                float4 w = *(const float4*)&Wp[k * 64 + tx * 4];
                ull w0 = dup2(w.x), w1 = dup2(w.y), w2 = dup2(w.z), w3 = dup2(w.w);
                ffma2(acc0[0], a01, w0); ffma2(acc1[0], a23, w0);
                ffma2(acc0[1], a01, w1); ffma2(acc1[1], a23, w1);
                ffma2(acc0[2], a01, w2); ffma2(acc1[2], a23, w2);
                ffma2(acc0[3], a01, w3); ffma2(acc1[3], a23, w3);
            }
            if (p == 0) __syncthreads();
        }

        float pg[4][4];
        #pragma unroll
        for (int g = 0; g < 4; g++) {
            float2 v0 = unpk(acc0[g]);
            float2 v1 = unpk(acc1[g]);
            const float* zf = (const float*)&zr[g];
            pg[0][g] = v0.x + zf[0]; pg[1][g] = v0.y + zf[1];
            pg[2][g] = v1.x + zf[2]; pg[3][g] = v1.y + zf[3];
        }
        float hreg[4];
        #pragma unroll
        for (int r = 0; r < 4; r++) {
            float cn = sigf(pg[r][1]) * creg[r] + sigf(pg[r][0]) * tanhf(pg[r][2]);
            hreg[r] = sigf(pg[r][3]) * tanhf(cn);
            creg[r] = cn;
        }
        float4 hv = make_float4(hreg[0], hreg[1], hreg[2], hreg[3]);
        __stcg((float4*)&hout[u * Bn + b0 + ty * 4], hv);
        *(float4*)&g_hsT[(size_t)u * TB + (size_t)t * Bn + b0 + ty * 4] = hv;

        if (t < Tn - 1) { grp_barrier(ctr, 32 * (s + 1)); s++; }
    }
}

// =================== latent stages ==========================================
__global__ void latent1(const float* __restrict__ W, const float* __restrict__ bias,
                        const float* __restrict__ eps,
                        float* __restrict__ zm, float* __restrict__ zl)
{
    int b = blockIdx.x, j = threadIdx.x;
    float sm = bias[j], sl = bias[j + Zn];
    for (int k = 0; k < Hn; k++) {
        float a = g_hfT[0][k * Bn + b];
        sm = fmaf(a, W[k * (2 * Zn) + j], sm);
        sl = fmaf(a, W[k * (2 * Zn) + Zn + j], sl);
    }
    for (int k = 0; k < Hn; k++) {
        float a = g_hbT[0][k * Bn + b];
        sm = fmaf(a, W[(Hn + k) * (2 * Zn) + j], sm);
        sl = fmaf(a, W[(Hn + k) * (2 * Zn) + Zn + j], sl);
    }
    zm[b * Zn + j] = sm;
    zl[b * Zn + j] = sl;
    g_z[b * Zn + j] = sm + expf(0.5f * sl) * eps[b * Zn + j];
}

__global__ void latent2(const float* __restrict__ init_W, const float* __restrict__ init_b,
                        const float* __restrict__ dec_Wx, const float* __restrict__ dec_b)
{
    int b = blockIdx.x;
    int col = blockIdx.y * 256 + threadIdx.x;
    __shared__ float zs[Zn];
    if (threadIdx.x < Zn) zs[threadIdx.x] = g_z[b * Zn + threadIdx.x];
    __syncthreads();
    if (col < 2 * Dn) {
        float s = init_b[col];
        for (int k = 0; k < Zn; k++) s = fmaf(zs[k], init_W[k * (2 * Dn) + col], s);
        s = tanhf(s);
        if (col < Dn) g_hdT[0][col * Bn + b] = s;
        else          g_cdT[(col - Dn) * Bn + b] = s;
    } else {
        int c2 = col - 2 * Dn;
        float s = dec_b[c2];
        for (int k = 0; k < Zn; k++) s = fmaf(zs[k], dec_Wx[(5 + k) * (4 * Dn) + c2], s);
        g_zgT[(size_t)c2 * Bn + b] = s;
    }
}

// =================== output head ============================================
__global__ __launch_bounds__(256) void mix_kernel(
    const float* __restrict__ Wm, const float* __restrict__ bm, float* __restrict__ out)
{
    __shared__ float As[32][33];
    __shared__ float Ws[32][128];
    __shared__ float ys[32 * 129];
    const int tid = threadIdx.x;
    const int tx = tid & 31, ty = tid >> 5;
    const int row0 = blockIdx.x * 32;
    float acc[4][4] = {};

    for (int k0 = 0; k0 < Dn; k0 += 32) {
        __syncthreads();
        {
            int k = tid >> 3, c = (tid & 7) * 4;
            float4 v = *(const float4*)&g_hsT[(size_t)(k0 + k) * TB + row0 + c];
            As[k][c] = v.x; As[k][c + 1] = v.y; As[k][c + 2] = v.z; As[k][c + 3] = v.w;
        }
        for (int i = tid; i < 32 * 128; i += 256) {
            int k = i >> 7, c = i & 127;
            Ws[k][c] = (c < Pn) ? Wm[(k0 + k) * Pn + c] : 0.f;
        }
        __syncthreads();
        #pragma unroll
        for (int k = 0; k < 32; k++) {
            float a0 = As[k][ty * 4 + 0], a1 = As[k][ty * 4 + 1];
            float a2 = As[k][ty * 4 + 2], a3 = As[k][ty * 4 + 3];
            float4 w = *(const float4*)&Ws[k][tx * 4];
            acc[0][0] = fmaf(a0, w.x, acc[0][0]); acc[0][1] = fmaf(a0, w.y, acc[0][1]);
            acc[0][2] = fmaf(a0, w.z, acc[0][2]); acc[0][3] = fmaf(a0, w.w, acc[0][3]);
            acc[1][0] = fmaf(a1, w.x, acc[1][0]); acc[1][1] = fmaf(a1, w.y, acc[1][1]);
            acc[1][2] = fmaf(a1, w.z, acc[1][2]); acc[1][3] = fmaf(a1, w.w, acc[1][3]);
            acc[2][0] = fmaf(a2, w.x, acc[2][0]); acc[2][1] = fmaf(a2, w.y, acc[2][1]);
            acc[2][2] = fmaf(a2, w.z, acc[2][2]); acc[2][3] = fmaf(a2, w.w, acc[2][3]);
            acc[3][0] = fmaf(a3, w.x, acc[3][0]); acc[3][1] = fmaf(a3, w.y, acc[3][1]);
            acc[3][2] = fmaf(a3, w.z, acc[3][2]); acc[3][3] = fmaf(a3, w.w, acc[3][3]);
        }
    }

    #pragma unroll
    for (int r = 0; r < 4; r++)
        #pragma unroll
        for (int c = 0; c < 4; c++) {
            int cc = tx * 4 + c;
            float v = acc[r][c] + ((cc < Pn) ? bm[cc] : 0.f);
            ys[(ty * 4 + r) * 129 + cc] = v;
        }
    __syncthreads();

    if (tid < 32) {
        int row = row0 + tid;
        int tt = row >> 8;
        int bb2 = row & 255;
        float* o = out + ((size_t)bb2 * Tn + tt) * Pn;
        const float* y = &ys[tid * 129];
        float m = y[0];
        #pragma unroll
        for (int j = 1; j < Kn; j++) m = fmaxf(m, y[j]);
        float e[Kn]; float sum = 0.f;
        #pragma unroll
        for (int j = 0; j < Kn; j++) { e[j] = expf(y[j] - m); sum += e[j]; }
        float inv = 1.f / sum;
        #pragma unroll
        for (int j = 0; j < Kn; j++) o[j] = e[j] * inv;
        #pragma unroll
        for (int j = Kn; j < 3 * Kn; j++) o[j] = y[j];
        #pragma unroll
        for (int j = 3 * Kn; j < 5 * Kn; j++) o[j] = expf(y[j]);
        #pragma unroll
        for (int j = 5 * Kn; j < 6 * Kn; j++) o[j] = tanhf(y[j]);
        o[120] = y[120]; o[121] = y[121]; o[122] = y[122];
    }
}

// =================== launcher ================================================
extern "C" void kernel_launch(void* const* d_in, const int* in_sizes, int n_in,
                              void* d_out, int out_size)
{
    (void)in_sizes; (void)n_in; (void)out_size;
    const float* data      = (const float*)d_in[0];
    const float* eps       = (const float*)d_in[1];
    const float* enc_Wx_f  = (const float*)d_in[2];
    const float* enc_Wh_f  = (const float*)d_in[3];
    const float* enc_b_f   = (const float*)d_in[4];
    const float* enc_Wx_b  = (const float*)d_in[5];
    const float* enc_Wh_b  = (const float*)d_in[6];
    const float* enc_b_b   = (const float*)d_in[7];
    const float* enc_out_W = (const float*)d_in[8];
    const float* enc_out_b = (const float*)d_in[9];
    const float* init_W    = (const float*)d_in[10];
    const float* init_b    = (const float*)d_in[11];
    const float* dec_Wx    = (const float*)d_in[12];
    const float* dec_Wh    = (const float*)d_in[13];
    const float* dec_b     = (const float*)d_in[14];
    const float* mix_W     = (const float*)d_in[15];
    const float* mix_b     = (const float*)d_in[16];
    float* out = (float*)d_out;

    cudaFuncSetAttribute(enc_persist, cudaFuncAttributeMaxDynamicSharedMemorySize, ENC_SMEM);
    cudaFuncSetAttribute(dec_persist, cudaFuncAttributeMaxDynamicSharedMemorySize, DEC_SMEM);

    const size_t params_sz = (size_t)Bn * Tn * Pn;

    init_bar<<<1, 32>>>();
    enc_persist<<<128, 256, ENC_SMEM>>>(data, enc_Wx_f, enc_Wh_f, enc_b_f,
                                        enc_Wx_b, enc_Wh_b, enc_b_b);
    latent1<<<Bn, 128>>>(enc_out_W, enc_out_b, eps,
                         out + params_sz, out + params_sz + (size_t)Bn * Zn);
    latent2<<<dim3(Bn, 12), 256>>>(init_W, init_b, dec_Wx, dec_b);
    dec_persist<<<128, 256, DEC_SMEM>>>(data, dec_Wx, dec_Wh);
    mix_kernel<<<TB / 32, 256>>>(mix_W, mix_b, out);
}